// round 10
// baseline (speedup 1.0000x reference)
#include <cuda_runtime.h>

// Problem constants
#define Bn   2
#define Cc   64
#define Oo   64
#define Gg   16
#define Ee   128
#define Tin  512
#define Wk   7
#define Dd   4
#define Tout 256
#define FO   64
#define PER  264   // padded de-interleaved row length (floats)

// Per-block BN-stat partials: [o][j], j = b*32 + d*8 + fh  (64 slots)
__device__ float  g_part1[Oo][64];
__device__ float  g_part2[Oo][64];
__device__ float2 g_ab[Oo];           // {a, bias56}

// ---------------------------------------------------------------------------
// Merged kernel: 3072 blocks, 128 threads. Interleaved 2 conv : 1 stats.
//   pos = bid%3: pos<2 -> conv tile cid = (bid/3)*2+pos (raw accumulator out)
//                pos==2 -> stats block sid = bid/3 (BN stat partials)
// Both paths read x; concurrent execution keeps x L2-resident (33.5MB < 126MB)
// so the chip pays first-touch DRAM only once.
// ---------------------------------------------------------------------------
__global__ __launch_bounds__(128) void merged_kernel(const float* __restrict__ x,
                                                     const float* __restrict__ wgt,
                                                     float* __restrict__ out) {
    __shared__ alignas(16) float pe[8][PER];
    __shared__ alignas(16) float pos_[8][PER];
    __shared__ alignas(16) float ws[8][4][8];   // [w0..w6, 0]
    __shared__ float s_p1[4], s_p2[4];

    const int bid  = blockIdx.x;
    const int grp  = bid / 3;
    const int pos3 = bid - grp * 3;
    const int tid  = threadIdx.x;
    const int lane = tid & 31;
    const int warp = tid >> 5;

    if (pos3 == 2) {
        // ================= STATS PATH (sid = grp, 16 rows) =================
        const int sid = grp;
        const int b   = sid >> 9;
        const int c   = (sid >> 3) & 63;
        const int fh  = sid & 7;
        const int sl   = lane & 7;
        const int gidx = lane >> 3;
        const int f    = fh * 16 + warp * 4 + gidx;

        if (tid < 4) { s_p1[tid] = 0.f; s_p2[tid] = 0.f; }
        __syncthreads();

        const float4* row = reinterpret_cast<const float4*>(
            &x[((b * Cc + c) * Ee + f) * Tin]);

        float se = 0.f, so = 0.f, se2 = 0.f, so2 = 0.f;
        float4 vfirst, vlast;
        {
            float4 v[8];
#pragma unroll
            for (int k = 0; k < 8; k++) v[k] = row[sl + 8 * k];
            vfirst = v[0];
#pragma unroll
            for (int k = 0; k < 8; k++) {
                float4 q = v[k];
                se += q.x + q.z;  so += q.y + q.w;
                se2 = fmaf(q.x, q.x, se2); se2 = fmaf(q.z, q.z, se2);
                so2 = fmaf(q.y, q.y, so2); so2 = fmaf(q.w, q.w, so2);
            }
        }
        {
            float4 v[8];
#pragma unroll
            for (int k = 0; k < 8; k++) v[k] = row[sl + 8 * (k + 8)];
            vlast = v[7];
#pragma unroll
            for (int k = 0; k < 8; k++) {
                float4 q = v[k];
                se += q.x + q.z;  so += q.y + q.w;
                se2 = fmaf(q.x, q.x, se2); se2 = fmaf(q.z, q.z, se2);
                so2 = fmaf(q.y, q.y, so2); so2 = fmaf(q.w, q.w, so2);
            }
        }

        const unsigned FULL = 0xffffffffu;
        const int base = lane & ~7;
        float x0   = __shfl_sync(FULL, vfirst.x, base);
        float x1   = __shfl_sync(FULL, vfirst.y, base);
        float x509 = __shfl_sync(FULL, vlast.y,  base + 7);
        float x510 = __shfl_sync(FULL, vlast.z,  base + 7);
        float x511 = __shfl_sync(FULL, vlast.w,  base + 7);

#pragma unroll
        for (int off = 1; off < 8; off <<= 1) {
            se  += __shfl_xor_sync(FULL, se,  off);
            so  += __shfl_xor_sync(FULL, so,  off);
            se2 += __shfl_xor_sync(FULL, se2, off);
            so2 += __shfl_xor_sync(FULL, so2, off);
        }

        float c1 = 0.f, c2 = 0.f;
        if (sl < 4) {
            float s1[7], s2[7];
            s1[0] = so - x509 - x511;  s2[0] = so2 - x509 * x509 - x511 * x511;
            s1[1] = se - x510;         s2[1] = se2 - x510 * x510;
            s1[2] = so - x511;         s2[2] = so2 - x511 * x511;
            s1[3] = se;                s2[3] = se2;
            s1[4] = so;                s2[4] = so2;
            s1[5] = se - x0;           s2[5] = se2 - x0 * x0;
            s1[6] = so - x1;           s2[6] = so2 - x1 * x1;

            const int g = c >> 2, d = c & 3;
            const int o = g * 4 + sl;
            const float* wp = &wgt[((o * Dd + d) * Ee + f) * Wk];
#pragma unroll
            for (int w = 0; w < 7; w++) {
                float wv = wp[w];
                c1 = fmaf(wv, s1[w], c1);
                c2 = fmaf(wv * wv, s2[w], c2);
            }
        }
        c1 += __shfl_xor_sync(FULL, c1, 8);
        c1 += __shfl_xor_sync(FULL, c1, 16);
        c2 += __shfl_xor_sync(FULL, c2, 8);
        c2 += __shfl_xor_sync(FULL, c2, 16);
        if (lane < 4) {
            atomicAdd(&s_p1[lane], c1);
            atomicAdd(&s_p2[lane], c2);
        }
        __syncthreads();
        if (tid < 4) {
            const int g = c >> 2, d = c & 3;
            const int j = b * 32 + d * 8 + fh;
            g_part1[g * 4 + tid][j] = s_p1[tid];
            g_part2[g * 4 + tid][j] = s_p2[tid];
        }
        return;
    }

    // ================= CONV PATH (raw accumulator) =================
    const int cid = grp * 2 + pos3;          // 0..2047
    const int b   = cid >> 10;
    const int g   = (cid >> 6) & 15;
    const int fo  = cid & 63;
    const int oc  = lane & 3;
    const int tc  = warp * 8 + (lane >> 2);  // 0..31; outputs t = 8tc..8tc+7

    // zero boundary slots {0,1,258..263} of each pe/pos_ row
    {
        int r  = tid >> 4;
        int s  = tid & 15;
        int ss = s & 7;
        int idx = (ss < 2) ? ss : (256 + ss);
        if (s < 8) pe[r][idx] = 0.f; else pos_[r][idx] = 0.f;
    }

    // de-interleaving fill
#pragma unroll
    for (int k = 0; k < 8; k++) {
        const int c = g * 4 + (k & 3);
        const int f = 2 * fo + (k >> 2);
        float4 v = reinterpret_cast<const float4*>(
            &x[((b * Cc + c) * Ee + f) * Tin])[tid];
        *reinterpret_cast<float2*>(&pe[k][2 * tid + 2])   = make_float2(v.y, v.w);
        *reinterpret_cast<float2*>(&pos_[k][2 * tid + 2]) = make_float2(v.x, v.z);
    }

    // weights
#pragma unroll
    for (int m = 0; m < 2; m++) {
        int j  = tid + 128 * m;
        int r  = j >> 5;
        int o2 = (j >> 3) & 3;
        int w  = j & 7;
        int d  = r & 3;
        int f2 = r >> 2;
        ws[r][o2][w] = (w < 7)
            ? wgt[(((g * 4 + o2) * Dd + d) * Ee + (2 * fo + f2)) * Wk + w] : 0.f;
    }
    __syncthreads();

    float acc[8];
#pragma unroll
    for (int j = 0; j < 8; j++) acc[j] = 0.f;

#pragma unroll
    for (int r = 0; r < 8; r++) {
        const float4* pe4  = reinterpret_cast<const float4*>(pe[r]);
        const float4* pos4 = reinterpret_cast<const float4*>(pos_[r]);
        float E[12], S[12];
        *reinterpret_cast<float4*>(&E[0]) = pe4[2 * tc];
        *reinterpret_cast<float4*>(&E[4]) = pe4[2 * tc + 1];
        *reinterpret_cast<float4*>(&E[8]) = pe4[2 * tc + 2];
        *reinterpret_cast<float4*>(&S[0]) = pos4[2 * tc];
        *reinterpret_cast<float4*>(&S[4]) = pos4[2 * tc + 1];
        *reinterpret_cast<float4*>(&S[8]) = pos4[2 * tc + 2];
        float4 wA = *reinterpret_cast<const float4*>(&ws[r][oc][0]);
        float4 wB = *reinterpret_cast<const float4*>(&ws[r][oc][4]);
#pragma unroll
        for (int j = 0; j < 8; j++) {
            acc[j] = fmaf(wA.x, E[j],     acc[j]);
            acc[j] = fmaf(wA.y, S[j + 1], acc[j]);
            acc[j] = fmaf(wA.z, E[j + 1], acc[j]);
            acc[j] = fmaf(wA.w, S[j + 2], acc[j]);
            acc[j] = fmaf(wB.x, E[j + 2], acc[j]);
            acc[j] = fmaf(wB.y, S[j + 3], acc[j]);
            acc[j] = fmaf(wB.z, E[j + 3], acc[j]);
        }
    }

    {
        int ob = ((b * Oo + g * 4 + oc) * FO + fo) * Tout + 8 * tc;
        *reinterpret_cast<float4*>(&out[ob])     = make_float4(acc[0], acc[1], acc[2], acc[3]);
        *reinterpret_cast<float4*>(&out[ob + 4]) = make_float4(acc[4], acc[5], acc[6], acc[7]);
    }
}

// ---------------------------------------------------------------------------
// Finalize: 1 block, 64 threads; thread o reduces its 64 partials -> g_ab.
// ---------------------------------------------------------------------------
__global__ __launch_bounds__(64) void finalize_kernel(const float* __restrict__ gamma,
                                                      const float* __restrict__ beta) {
    const int o = threadIdx.x;
    const float4* p1v = reinterpret_cast<const float4*>(g_part1[o]);
    const float4* p2v = reinterpret_cast<const float4*>(g_part2[o]);
    float p1 = 0.f, p2 = 0.f;
#pragma unroll
    for (int k = 0; k < 16; k++) {
        float4 a = p1v[k], b = p2v[k];
        p1 += (a.x + a.y) + (a.z + a.w);
        p2 += (b.x + b.y) + (b.z + b.w);
    }
    const float M = 1835008.f;   // B*D*E*t*W
    float mean = p1 / M;
    float var  = p2 / M - mean * mean;
    float a    = gamma[o] * rsqrtf(var + 1e-5f);
    g_ab[o] = make_float2(a, 56.f * (beta[o] - mean * a));
}

// ---------------------------------------------------------------------------
// Apply: gateless in-place affine + LeakyReLU on out (L2-warm).
// Block = (b, o, q): 1024 blocks, 128 threads, 4 float4/thread.
// ---------------------------------------------------------------------------
__global__ __launch_bounds__(128) void apply_kernel(float* __restrict__ out) {
    const int bid = blockIdx.x;
    const int b   = bid >> 9;
    const int o   = (bid >> 3) & 63;
    const int q   = bid & 7;
    const int tid = threadIdx.x;

    const float2 ab = g_ab[o];
    float4* o4 = reinterpret_cast<float4*>(out);
    const int base = (b * Oo + o) * 4096 + q * 512 + tid;

    float4 v[4];
#pragma unroll
    for (int k = 0; k < 4; k++) v[k] = o4[base + 128 * k];
#pragma unroll
    for (int k = 0; k < 4; k++) {
        float4 r;
        r.x = fmaf(ab.x, v[k].x, ab.y);
        r.y = fmaf(ab.x, v[k].y, ab.y);
        r.z = fmaf(ab.x, v[k].z, ab.y);
        r.w = fmaf(ab.x, v[k].w, ab.y);
        r.x = (r.x >= 0.f) ? r.x : 0.01f * r.x;
        r.y = (r.y >= 0.f) ? r.y : 0.01f * r.y;
        r.z = (r.z >= 0.f) ? r.z : 0.01f * r.z;
        r.w = (r.w >= 0.f) ? r.w : 0.01f * r.w;
        o4[base + 128 * k] = r;
    }
}

extern "C" void kernel_launch(void* const* d_in, const int* in_sizes, int n_in,
                              void* d_out, int out_size) {
    const float* x     = (const float*)d_in[0];
    const float* wgt   = (const float*)d_in[1];
    const float* gamma = (const float*)d_in[2];
    const float* beta  = (const float*)d_in[3];

    merged_kernel<<<3072, 128>>>(x, wgt, (float*)d_out);
    finalize_kernel<<<1, 64>>>(gamma, beta);
    apply_kernel<<<1024, 128>>>((float*)d_out);
}